// round 1
// baseline (speedup 1.0000x reference)
#include <cuda_runtime.h>
#include <cuda_bf16.h>
#include <math.h>

// ---------------- problem constants ----------------
#define BB 16
#define NN 1024
#define CC_IN 768
#define DD 512
#define DEPTH 4
#define HP 32
#define WP 32
#define MTOT (BB * NN)          // 16384 rows
#define XSZ (MTOT * DD)         // 8388608 elems per activation map

// ---------------- device scratch (static, allowed) ----------------
__device__ float g_x[XSZ];
__device__ float g_h[XSZ];
__device__ float g_xin[XSZ];
__device__ float g_gate[XSZ];
__device__ float g_u[XSZ];
__device__ float g_yacc[XSZ];
__device__ float g_yg[XSZ];
__device__ float g_ap[NN * DD];     // a_pow table (t, d)
__device__ float g_iap[NN * DD];    // 1 / a_pow

// ---------------- GEMM: C = A(MxK) @ B(KxN) (+epilogue) ----------------
// BM=128, BN=64, BK=16, 256 threads, each thread 8x4 micro-tile.
// EPI 0: C0[m*N+n]     = acc + bias[n]
// EPI 1: n<512 -> C0[m*512+n] = acc+bias ; else C1[m*512+n-512] = sigmoid(acc+bias)
// EPI 2: C0[m*512+n]  += acc + bias[n]   (residual, read+write)
template <int EPI>
__global__ __launch_bounds__(256) void gemm_kernel(
    const float* __restrict__ A, const float* __restrict__ B,
    const float* __restrict__ bias, float* __restrict__ C0,
    float* __restrict__ C1, int M, int N, int K)
{
    __shared__ __align__(16) float As[16][132];  // [k][m], padded
    __shared__ __align__(16) float Bs[16][64];   // [k][n]

    const int tid = threadIdx.x;
    const int bx = blockIdx.x;   // N tiles
    const int by = blockIdx.y;   // M tiles
    const int tx = tid & 15;     // n dir
    const int ty = tid >> 4;     // m dir
    const int ktiles = K >> 4;

    const int arow = tid >> 2;          // 0..63
    const int acol = (tid & 3) << 2;    // 0,4,8,12
    const int brow = tid >> 4;          // 0..15
    const int bcol = (tid & 15) << 2;   // 0..60

    const float* Aptr = A + (size_t)by * 128 * K;
    const float* Bptr = B + (size_t)bx * 64;

    float c[8][4];
#pragma unroll
    for (int i = 0; i < 8; i++)
#pragma unroll
        for (int j = 0; j < 4; j++) c[i][j] = 0.f;

    // initial tile load
    {
        float4 v0 = *(const float4*)(Aptr + (size_t)arow * K + acol);
        float4 v1 = *(const float4*)(Aptr + (size_t)(arow + 64) * K + acol);
        As[acol + 0][arow] = v0.x; As[acol + 1][arow] = v0.y;
        As[acol + 2][arow] = v0.z; As[acol + 3][arow] = v0.w;
        As[acol + 0][arow + 64] = v1.x; As[acol + 1][arow + 64] = v1.y;
        As[acol + 2][arow + 64] = v1.z; As[acol + 3][arow + 64] = v1.w;
        float4 bv = *(const float4*)(Bptr + (size_t)brow * N + bcol);
        *(float4*)&Bs[brow][bcol] = bv;
    }
    __syncthreads();

    float4 pa0, pa1, pb;
    for (int kt = 0; kt < ktiles; kt++) {
        const bool has_next = (kt + 1) < ktiles;
        if (has_next) {
            const float* Ap = Aptr + (kt + 1) * 16;
            pa0 = *(const float4*)(Ap + (size_t)arow * K + acol);
            pa1 = *(const float4*)(Ap + (size_t)(arow + 64) * K + acol);
            pb  = *(const float4*)(Bptr + (size_t)((kt + 1) * 16 + brow) * N + bcol);
        }
#pragma unroll
        for (int k = 0; k < 16; k++) {
            float4 a0 = *(const float4*)&As[k][ty * 8];
            float4 a1 = *(const float4*)&As[k][ty * 8 + 4];
            float4 b0 = *(const float4*)&Bs[k][tx * 4];
            float av[8] = {a0.x, a0.y, a0.z, a0.w, a1.x, a1.y, a1.z, a1.w};
            float bv[4] = {b0.x, b0.y, b0.z, b0.w};
#pragma unroll
            for (int i = 0; i < 8; i++)
#pragma unroll
                for (int j = 0; j < 4; j++) c[i][j] = fmaf(av[i], bv[j], c[i][j]);
        }
        __syncthreads();
        if (has_next) {
            As[acol + 0][arow] = pa0.x; As[acol + 1][arow] = pa0.y;
            As[acol + 2][arow] = pa0.z; As[acol + 3][arow] = pa0.w;
            As[acol + 0][arow + 64] = pa1.x; As[acol + 1][arow + 64] = pa1.y;
            As[acol + 2][arow + 64] = pa1.z; As[acol + 3][arow + 64] = pa1.w;
            *(float4*)&Bs[brow][bcol] = pb;
            __syncthreads();
        }
    }

    // epilogue
    const int gn = bx * 64 + tx * 4;
    float4 b4 = *(const float4*)(bias + gn);
#pragma unroll
    for (int i = 0; i < 8; i++) {
        size_t m = (size_t)by * 128 + ty * 8 + i;
        float v0 = c[i][0] + b4.x;
        float v1 = c[i][1] + b4.y;
        float v2 = c[i][2] + b4.z;
        float v3 = c[i][3] + b4.w;
        if (EPI == 0) {
            *(float4*)(C0 + m * N + gn) = make_float4(v0, v1, v2, v3);
        } else if (EPI == 1) {
            if (gn < 512) {
                *(float4*)(C0 + m * 512 + gn) = make_float4(v0, v1, v2, v3);
            } else {
                float s0 = 1.f / (1.f + expf(-v0));
                float s1 = 1.f / (1.f + expf(-v1));
                float s2 = 1.f / (1.f + expf(-v2));
                float s3 = 1.f / (1.f + expf(-v3));
                *(float4*)(C1 + m * 512 + (gn - 512)) = make_float4(s0, s1, s2, s3);
            }
        } else {
            size_t o = m * 512 + gn;
            float4 r = *(const float4*)(C0 + o);
            *(float4*)(C0 + o) = make_float4(r.x + v0, r.y + v1, r.z + v2, r.w + v3);
        }
    }
}

// ---------------- LayerNorm: one warp per row of 512 ----------------
__global__ __launch_bounds__(256) void ln_kernel(
    const float* __restrict__ x, const float* __restrict__ w,
    const float* __restrict__ b, float* __restrict__ out)
{
    const int warp = threadIdx.x >> 5;
    const int lane = threadIdx.x & 31;
    const size_t row = (size_t)blockIdx.x * 8 + warp;
    const float4* xr = (const float4*)(x + row * 512);

    float4 v[4];
    float sum = 0.f;
#pragma unroll
    for (int q = 0; q < 4; q++) {
        v[q] = xr[lane + q * 32];
        sum += v[q].x + v[q].y + v[q].z + v[q].w;
    }
#pragma unroll
    for (int o = 16; o > 0; o >>= 1) sum += __shfl_xor_sync(0xffffffffu, sum, o);
    const float mu = sum * (1.f / 512.f);

    float sq = 0.f;
#pragma unroll
    for (int q = 0; q < 4; q++) {
        float dx = v[q].x - mu, dy = v[q].y - mu, dz = v[q].z - mu, dw = v[q].w - mu;
        sq += dx * dx + dy * dy + dz * dz + dw * dw;
    }
#pragma unroll
    for (int o = 16; o > 0; o >>= 1) sq += __shfl_xor_sync(0xffffffffu, sq, o);
    const float rstd = rsqrtf(sq * (1.f / 512.f) + 1e-5f);

    float4* orow = (float4*)(out + row * 512);
    const float4* wr = (const float4*)w;
    const float4* br = (const float4*)b;
#pragma unroll
    for (int q = 0; q < 4; q++) {
        float4 w4 = wr[lane + q * 32];
        float4 b4 = br[lane + q * 32];
        float4 o4;
        o4.x = (v[q].x - mu) * rstd * w4.x + b4.x;
        o4.y = (v[q].y - mu) * rstd * w4.y + b4.y;
        o4.z = (v[q].z - mu) * rstd * w4.z + b4.z;
        o4.w = (v[q].w - mu) * rstd * w4.w + b4.w;
        orow[lane + q * 32] = o4;
    }
}

// ---------------- depthwise 3x3 conv + bias + SiLU ----------------
__global__ __launch_bounds__(256) void conv_kernel(
    const float* __restrict__ xin, const float* __restrict__ cw,
    const float* __restrict__ cb, float* __restrict__ u)
{
    const int gid = blockIdx.x * 256 + threadIdx.x;  // over 8.4M
    const int d = gid & 511;
    const int pos = gid >> 9;
    const int j = pos & 31;
    const int i = (pos >> 5) & 31;
    const int b = pos >> 10;

    float acc = cb[d];
#pragma unroll
    for (int di = 0; di < 3; di++) {
        const int ii = i + di - 1;
        if (ii < 0 || ii >= 32) continue;
#pragma unroll
        for (int dj = 0; dj < 3; dj++) {
            const int jj = j + dj - 1;
            if (jj < 0 || jj >= 32) continue;
            acc = fmaf(xin[(((size_t)b * 32 + ii) * 32 + jj) * 512 + d],
                       cw[(di * 3 + dj) * 512 + d], acc);
        }
    }
    u[(size_t)gid] = acc / (1.f + expf(-acc));  // SiLU
}

// ---------------- a_pow table ----------------
__global__ __launch_bounds__(256) void ap_kernel(const float* __restrict__ a_logit)
{
    const int gid = blockIdx.x * 256 + threadIdx.x;  // NN*DD threads
    const int d = gid & 511;
    const int t = gid >> 9;
    const float al = a_logit[d];
    float a = 1.f / (1.f + expf(-al));
    a = fminf(fmaxf(a, 1e-4f), 1.f - 1e-4f);
    const float ap = fmaxf(expf((float)t * logf(a)), 1e-20f);
    g_ap[gid] = ap;
    g_iap[gid] = 1.f / ap;
}

// ---------------- SSM scans ----------------
// row scan (writes): y = 0.25*cc*s_f + 0.5*dd*x ; then += 0.25*cc*s_b
__global__ __launch_bounds__(64) void scan_row_kernel(
    const float* __restrict__ u, const float* __restrict__ sb,
    const float* __restrict__ sc, const float* __restrict__ sd,
    float* __restrict__ yacc)
{
    const int g = blockIdx.x * 64 + threadIdx.x;  // 8192 threads
    const int d = g & 511;
    const int b = g >> 9;
    const float bb = sb[d], cc25 = 0.25f * sc[d], dd5 = 0.5f * sd[d];
    const size_t base = (size_t)b * 1024 * 512 + d;

    float r = 0.f;
    for (int t = 0; t < 1024; t++) {
        const size_t idx = base + (size_t)t * 512;
        const float xv = u[idx];
        r = fmaf(xv * bb, g_iap[t * 512 + d], r);
        yacc[idx] = cc25 * (r * g_ap[t * 512 + d]) + dd5 * xv;
    }
    r = 0.f;
    for (int t = 0; t < 1024; t++) {
        const int pos = 1023 - t;
        const size_t idx = base + (size_t)pos * 512;
        const float xv = u[idx];
        r = fmaf(xv * bb, g_iap[t * 512 + d], r);
        yacc[idx] += cc25 * (r * g_ap[t * 512 + d]);
    }
}

// col scan (adds), final pass multiplies gate -> yg
__global__ __launch_bounds__(64) void scan_col_kernel(
    const float* __restrict__ u, const float* __restrict__ sb,
    const float* __restrict__ sc, const float* __restrict__ sd,
    const float* __restrict__ gate, float* __restrict__ yacc,
    float* __restrict__ yg)
{
    const int g = blockIdx.x * 64 + threadIdx.x;
    const int d = g & 511;
    const int b = g >> 9;
    const float bb = sb[d], cc25 = 0.25f * sc[d], dd5 = 0.5f * sd[d];
    const size_t base = (size_t)b * 1024 * 512 + d;

    float r = 0.f;
    for (int t = 0; t < 1024; t++) {
        const int s = ((t & 31) << 5) + (t >> 5);      // (h=t%32, w=t/32)
        const size_t idx = base + (size_t)s * 512;
        const float xv = u[idx];
        r = fmaf(xv * bb, g_iap[t * 512 + d], r);
        yacc[idx] += cc25 * (r * g_ap[t * 512 + d]) + dd5 * xv;
    }
    r = 0.f;
    for (int t = 0; t < 1024; t++) {
        const int tp = 1023 - t;
        const int s = ((tp & 31) << 5) + (tp >> 5);
        const size_t idx = base + (size_t)s * 512;
        const float xv = u[idx];
        r = fmaf(xv * bb, g_iap[t * 512 + d], r);
        const float val = yacc[idx] + cc25 * (r * g_ap[t * 512 + d]);
        yg[idx] = val * gate[idx];
    }
}

// ---------------- final pool: mean over 1024 positions ----------------
__global__ __launch_bounds__(512) void pool_kernel(const float* __restrict__ h,
                                                   float* __restrict__ out)
{
    const int b = blockIdx.x;   // 16
    const int d = threadIdx.x;  // 512
    const float* p = h + (size_t)b * 1024 * 512 + d;
    float s = 0.f;
    for (int n = 0; n < 1024; n++) s += p[(size_t)n * 512];
    out[b * 512 + d] = s * (1.f / 1024.f);
}

// ---------------- host launch ----------------
extern "C" void kernel_launch(void* const* d_in, const int* in_sizes, int n_in,
                              void* d_out, int out_size)
{
    const float* tokens    = (const float*)d_in[0];
    const float* in_proj_w = (const float*)d_in[1];
    const float* in_proj_b = (const float*)d_in[2];
    const float* nw        = (const float*)d_in[3];
    const float* nb        = (const float*)d_in[4];
    const float* iw        = (const float*)d_in[5];
    const float* ib        = (const float*)d_in[6];
    const float* cw        = (const float*)d_in[7];
    const float* cb        = (const float*)d_in[8];
    const float* al        = (const float*)d_in[9];
    const float* sb        = (const float*)d_in[10];
    const float* sc        = (const float*)d_in[11];
    const float* sd        = (const float*)d_in[12];
    const float* ow        = (const float*)d_in[13];
    const float* ob        = (const float*)d_in[14];
    const float* onw       = (const float*)d_in[15];
    const float* onb       = (const float*)d_in[16];
    float* out = (float*)d_out;

    float *px, *ph, *pxin, *pgate, *pu, *pyacc, *pyg;
    cudaGetSymbolAddress((void**)&px, g_x);
    cudaGetSymbolAddress((void**)&ph, g_h);
    cudaGetSymbolAddress((void**)&pxin, g_xin);
    cudaGetSymbolAddress((void**)&pgate, g_gate);
    cudaGetSymbolAddress((void**)&pu, g_u);
    cudaGetSymbolAddress((void**)&pyacc, g_yacc);
    cudaGetSymbolAddress((void**)&pyg, g_yg);

    // in_proj: x = tokens @ in_proj_w + b   (M=16384, N=512, K=768)
    {
        dim3 grid(512 / 64, MTOT / 128);
        gemm_kernel<0><<<grid, 256>>>(tokens, in_proj_w, in_proj_b, px, nullptr,
                                      MTOT, 512, CC_IN);
    }

    for (int i = 0; i < DEPTH; i++) {
        // LayerNorm
        ln_kernel<<<MTOT / 8, 256>>>(px, nw + i * 512, nb + i * 512, ph);
        // inp GEMM -> xin, gate (M=16384, N=1024, K=512)
        {
            dim3 grid(1024 / 64, MTOT / 128);
            gemm_kernel<1><<<grid, 256>>>(ph, iw + (size_t)i * 512 * 1024,
                                          ib + i * 1024, pxin, pgate,
                                          MTOT, 1024, 512);
        }
        // depthwise conv + SiLU
        conv_kernel<<<XSZ / 256, 256>>>(pxin, cw + i * 9 * 512, cb + i * 512, pu);
        // a_pow tables for this block
        ap_kernel<<<(NN * DD) / 256, 256>>>(al + i * 512);
        // scans
        scan_row_kernel<<<8192 / 64, 64>>>(pu, sb + i * 512, sc + i * 512,
                                           sd + i * 512, pyacc);
        scan_col_kernel<<<8192 / 64, 64>>>(pu, sb + i * 512, sc + i * 512,
                                           sd + i * 512, pgate, pyacc, pyg);
        // out GEMM + residual (M=16384, N=512, K=512)
        {
            dim3 grid(512 / 64, MTOT / 128);
            gemm_kernel<2><<<grid, 256>>>(pyg, ow + (size_t)i * 512 * 512,
                                          ob + i * 512, px, nullptr,
                                          MTOT, 512, 512);
        }
    }

    // final LN + pooled mean
    ln_kernel<<<MTOT / 8, 256>>>(px, onw, onb, ph);
    pool_kernel<<<16, 512>>>(ph, out);
}

// round 3
// speedup vs baseline: 2.2274x; 2.2274x over previous
#include <cuda_runtime.h>
#include <cuda_bf16.h>
#include <math.h>

// ---------------- problem constants ----------------
#define BB 16
#define NN 1024
#define CC_IN 768
#define DD 512
#define DEPTH 4
#define MTOT (BB * NN)          // 16384 rows
#define XSZ (MTOT * DD)         // 8388608 elems per activation map

// ---------------- device scratch ----------------
__device__ float g_x[XSZ];
__device__ float g_h[XSZ];
__device__ float g_xin[XSZ];
__device__ float g_gate[XSZ];
__device__ float g_u[XSZ];
__device__ float g_yg[XSZ];
__device__ float g_s0[XSZ];
__device__ float g_s1[XSZ];
__device__ float g_s2[XSZ];
__device__ float g_s3[XSZ];
__device__ float g_ap[NN * DD];     // a_pow table (t, d)
__device__ float g_iap[NN * DD];    // 1 / a_pow

// ---------------- helpers ----------------
__device__ __forceinline__ unsigned f2tf(float x) {
    unsigned u;
    asm("cvt.rna.tf32.f32 %0, %1;" : "=r"(u) : "f"(x));
    return u;
}
__device__ __forceinline__ void cp_async16(void* smem, const void* gmem) {
    unsigned s = (unsigned)__cvta_generic_to_shared(smem);
    asm volatile("cp.async.cg.shared.global [%0], [%1], 16;\n" :: "r"(s), "l"(gmem));
}
#define CP_COMMIT asm volatile("cp.async.commit_group;\n" ::: "memory")
#define CP_WAIT1  asm volatile("cp.async.wait_group 1;\n" ::: "memory")
#define CP_WAIT0  asm volatile("cp.async.wait_group 0;\n" ::: "memory")

__device__ __forceinline__ void mma_tf32(float* c, const unsigned* a, const unsigned* b) {
    asm volatile(
        "mma.sync.aligned.m16n8k8.row.col.f32.tf32.tf32.f32 "
        "{%0,%1,%2,%3}, {%4,%5,%6,%7}, {%8,%9}, {%0,%1,%2,%3};"
        : "+f"(c[0]), "+f"(c[1]), "+f"(c[2]), "+f"(c[3])
        : "r"(a[0]), "r"(a[1]), "r"(a[2]), "r"(a[3]), "r"(b[0]), "r"(b[1]));
}

// ---------------- TF32 tensor-core GEMM ----------------
// C = A(MxK) @ B(KxN) + bias, tiles BM=128 BN=128 BK=16, 256 threads.
// EPI 0: C0[m*N+n]    = v
// EPI 1: n<512 -> C0[m*512+n]=v ; else C1[m*512+n-512]=sigmoid(v)   (N=1024)
// EPI 2: C0[m*512+n] += v   (residual)
template <int EPI>
__global__ __launch_bounds__(256) void gemm_tc_kernel(
    const float* __restrict__ A, const float* __restrict__ B,
    const float* __restrict__ bias, float* __restrict__ C0,
    float* __restrict__ C1, int N, int K)
{
    __shared__ float As[2][128][20];
    __shared__ float Bs[2][16][136];

    const int tid = threadIdx.x;
    const int bx = blockIdx.x;
    const int by = blockIdx.y;
    const int wid = tid >> 5;
    const int lane = tid & 31;
    const int grp = lane >> 2;      // 0..7
    const int thr = lane & 3;       // 0..3
    const int wm = (wid >> 2) * 64; // warp m offset
    const int wn = (wid & 3) * 32;  // warp n offset
    const int ktiles = K >> 4;

    const float* Aptr = A + (size_t)by * 128 * K;
    const float* Bptr = B + (size_t)bx * 128;

    float c[4][4][4];
#pragma unroll
    for (int i = 0; i < 4; i++)
#pragma unroll
        for (int j = 0; j < 4; j++)
#pragma unroll
            for (int q = 0; q < 4; q++) c[i][j][q] = 0.f;

    // tile loader
    auto load_tiles = [&](int kt, int s) {
#pragma unroll
        for (int j = 0; j < 2; j++) {
            int idx = tid * 2 + j;
            int ar = idx >> 2, ac = (idx & 3) * 4;
            cp_async16(&As[s][ar][ac], Aptr + (size_t)ar * K + kt * 16 + ac);
            int br = idx >> 5, bc = (idx & 31) * 4;
            cp_async16(&Bs[s][br][bc], Bptr + (size_t)(kt * 16 + br) * N + bc);
        }
    };

    load_tiles(0, 0);
    CP_COMMIT;

    for (int kt = 0; kt < ktiles; kt++) {
        if (kt + 1 < ktiles) {
            load_tiles(kt + 1, (kt + 1) & 1);
            CP_COMMIT;
            CP_WAIT1;
        } else {
            CP_WAIT0;
        }
        __syncthreads();

        const int s = kt & 1;
#pragma unroll
        for (int ks = 0; ks < 2; ks++) {
            const int k0 = ks * 8;
            unsigned a[4][4], b[4][2];
#pragma unroll
            for (int i = 0; i < 4; i++) {
                const int r0 = wm + i * 16 + grp;
                a[i][0] = f2tf(As[s][r0][k0 + thr]);
                a[i][1] = f2tf(As[s][r0 + 8][k0 + thr]);
                a[i][2] = f2tf(As[s][r0][k0 + thr + 4]);
                a[i][3] = f2tf(As[s][r0 + 8][k0 + thr + 4]);
            }
#pragma unroll
            for (int j = 0; j < 4; j++) {
                const int cn = wn + j * 8 + grp;
                b[j][0] = f2tf(Bs[s][k0 + thr][cn]);
                b[j][1] = f2tf(Bs[s][k0 + thr + 4][cn]);
            }
#pragma unroll
            for (int i = 0; i < 4; i++)
#pragma unroll
                for (int j = 0; j < 4; j++) mma_tf32(c[i][j], a[i], b[j]);
        }
        __syncthreads();
    }

    // epilogue
#pragma unroll
    for (int j = 0; j < 4; j++) {
        const int gcol = bx * 128 + wn + j * 8 + thr * 2;
        const float2 bv = *(const float2*)(bias + gcol);
#pragma unroll
        for (int i = 0; i < 4; i++) {
            const size_t grow0 = (size_t)by * 128 + wm + i * 16 + grp;
            const size_t grow1 = grow0 + 8;
            float v00 = c[i][j][0] + bv.x, v01 = c[i][j][1] + bv.y;
            float v10 = c[i][j][2] + bv.x, v11 = c[i][j][3] + bv.y;
            if (EPI == 0) {
                *(float2*)(C0 + grow0 * N + gcol) = make_float2(v00, v01);
                *(float2*)(C0 + grow1 * N + gcol) = make_float2(v10, v11);
            } else if (EPI == 1) {
                if (gcol < 512) {
                    *(float2*)(C0 + grow0 * 512 + gcol) = make_float2(v00, v01);
                    *(float2*)(C0 + grow1 * 512 + gcol) = make_float2(v10, v11);
                } else {
                    const int gc = gcol - 512;
                    *(float2*)(C1 + grow0 * 512 + gc) = make_float2(
                        1.f / (1.f + expf(-v00)), 1.f / (1.f + expf(-v01)));
                    *(float2*)(C1 + grow1 * 512 + gc) = make_float2(
                        1.f / (1.f + expf(-v10)), 1.f / (1.f + expf(-v11)));
                }
            } else {
                size_t o0 = grow0 * 512 + gcol, o1 = grow1 * 512 + gcol;
                float2 r0 = *(const float2*)(C0 + o0);
                float2 r1 = *(const float2*)(C0 + o1);
                *(float2*)(C0 + o0) = make_float2(r0.x + v00, r0.y + v01);
                *(float2*)(C0 + o1) = make_float2(r1.x + v10, r1.y + v11);
            }
        }
    }
}

// ---------------- LayerNorm: one warp per row of 512 ----------------
__global__ __launch_bounds__(256) void ln_kernel(
    const float* __restrict__ x, const float* __restrict__ w,
    const float* __restrict__ b, float* __restrict__ out)
{
    const int warp = threadIdx.x >> 5;
    const int lane = threadIdx.x & 31;
    const size_t row = (size_t)blockIdx.x * 8 + warp;
    const float4* xr = (const float4*)(x + row * 512);

    float4 v[4];
    float sum = 0.f;
#pragma unroll
    for (int q = 0; q < 4; q++) {
        v[q] = xr[lane + q * 32];
        sum += v[q].x + v[q].y + v[q].z + v[q].w;
    }
#pragma unroll
    for (int o = 16; o > 0; o >>= 1) sum += __shfl_xor_sync(0xffffffffu, sum, o);
    const float mu = sum * (1.f / 512.f);

    float sq = 0.f;
#pragma unroll
    for (int q = 0; q < 4; q++) {
        float dx = v[q].x - mu, dy = v[q].y - mu, dz = v[q].z - mu, dw = v[q].w - mu;
        sq += dx * dx + dy * dy + dz * dz + dw * dw;
    }
#pragma unroll
    for (int o = 16; o > 0; o >>= 1) sq += __shfl_xor_sync(0xffffffffu, sq, o);
    const float rstd = rsqrtf(sq * (1.f / 512.f) + 1e-5f);

    float4* orow = (float4*)(out + row * 512);
    const float4* wr = (const float4*)w;
    const float4* br = (const float4*)b;
#pragma unroll
    for (int q = 0; q < 4; q++) {
        float4 w4 = wr[lane + q * 32];
        float4 b4 = br[lane + q * 32];
        float4 o4;
        o4.x = (v[q].x - mu) * rstd * w4.x + b4.x;
        o4.y = (v[q].y - mu) * rstd * w4.y + b4.y;
        o4.z = (v[q].z - mu) * rstd * w4.z + b4.z;
        o4.w = (v[q].w - mu) * rstd * w4.w + b4.w;
        orow[lane + q * 32] = o4;
    }
}

// ---------------- depthwise 3x3 conv + bias + SiLU ----------------
__global__ __launch_bounds__(256) void conv_kernel(
    const float* __restrict__ xin, const float* __restrict__ cw,
    const float* __restrict__ cb, float* __restrict__ u)
{
    const int gid = blockIdx.x * 256 + threadIdx.x;
    const int d = gid & 511;
    const int pos = gid >> 9;
    const int j = pos & 31;
    const int i = (pos >> 5) & 31;
    const int b = pos >> 10;

    float acc = cb[d];
#pragma unroll
    for (int di = 0; di < 3; di++) {
        const int ii = i + di - 1;
        if (ii < 0 || ii >= 32) continue;
#pragma unroll
        for (int dj = 0; dj < 3; dj++) {
            const int jj = j + dj - 1;
            if (jj < 0 || jj >= 32) continue;
            acc = fmaf(xin[(((size_t)b * 32 + ii) * 32 + jj) * 512 + d],
                       cw[(di * 3 + dj) * 512 + d], acc);
        }
    }
    u[(size_t)gid] = acc / (1.f + expf(-acc));
}

// ---------------- a_pow table ----------------
__global__ __launch_bounds__(256) void ap_kernel(const float* __restrict__ a_logit)
{
    const int gid = blockIdx.x * 256 + threadIdx.x;
    const int d = gid & 511;
    const int t = gid >> 9;
    const float al = a_logit[d];
    float a = 1.f / (1.f + expf(-al));
    a = fminf(fmaxf(a, 1e-4f), 1.f - 1e-4f);
    const float ap = fmaxf(expf((float)t * logf(a)), 1e-20f);
    g_ap[gid] = ap;
    g_iap[gid] = 1.f / ap;
}

// ---------------- 4-direction SSM scan (pure cumsum form) ----------------
// dir 0: row fwd   pos = t
// dir 1: row bwd   pos = 1023-t
// dir 2: col fwd   pos = ((t&31)<<5)+(t>>5)
// dir 3: col bwd   pos of (1023-t) col-mapped
__global__ __launch_bounds__(128) void scan4_kernel(
    const float* __restrict__ u, const float* __restrict__ sb,
    float* __restrict__ s0, float* __restrict__ s1,
    float* __restrict__ s2, float* __restrict__ s3)
{
    const int gid = blockIdx.x * 128 + threadIdx.x;   // 32768 threads
    const int dir = gid >> 13;
    const int r = gid & 8191;
    const int d = r & 511;
    const int b = r >> 9;
    const float bb = sb[d];
    const size_t base = (size_t)b * (1024 * 512) + d;
    float* outb = (dir == 0) ? s0 : (dir == 1) ? s1 : (dir == 2) ? s2 : s3;

    float racc = 0.f;
#pragma unroll 4
    for (int t = 0; t < 1024; t++) {
        int pos;
        if (dir == 0)      pos = t;
        else if (dir == 1) pos = 1023 - t;
        else if (dir == 2) pos = ((t & 31) << 5) + (t >> 5);
        else { const int tp = 1023 - t; pos = ((tp & 31) << 5) + (tp >> 5); }
        const size_t idx = base + (size_t)pos * 512;
        racc = fmaf(u[idx] * bb, g_iap[t * 512 + d], racc);
        outb[idx] = racc * g_ap[t * 512 + d];
    }
}

// ---------------- merge: y = 0.25*cc*(s0+s1+s2+s3) + dd*u ; *gate ----------------
__global__ __launch_bounds__(256) void merge_kernel(
    const float* __restrict__ s0, const float* __restrict__ s1,
    const float* __restrict__ s2, const float* __restrict__ s3,
    const float* __restrict__ u, const float* __restrict__ gate,
    const float* __restrict__ sc, const float* __restrict__ sd,
    float* __restrict__ yg)
{
    const int idx = blockIdx.x * 256 + threadIdx.x;
    const int d = idx & 511;
    const float y = 0.25f * sc[d] * (s0[idx] + s1[idx] + s2[idx] + s3[idx])
                  + sd[d] * u[idx];
    yg[idx] = y * gate[idx];
}

// ---------------- final pool ----------------
__global__ __launch_bounds__(512) void pool_kernel(const float* __restrict__ h,
                                                   float* __restrict__ out)
{
    const int b = blockIdx.x;
    const int d = threadIdx.x;
    const float* p = h + (size_t)b * 1024 * 512 + d;
    float s = 0.f;
    for (int n = 0; n < 1024; n++) s += p[(size_t)n * 512];
    out[b * 512 + d] = s * (1.f / 1024.f);
}

// ---------------- host launch ----------------
extern "C" void kernel_launch(void* const* d_in, const int* in_sizes, int n_in,
                              void* d_out, int out_size)
{
    const float* tokens    = (const float*)d_in[0];
    const float* in_proj_w = (const float*)d_in[1];
    const float* in_proj_b = (const float*)d_in[2];
    const float* nw        = (const float*)d_in[3];
    const float* nb        = (const float*)d_in[4];
    const float* iw        = (const float*)d_in[5];
    const float* ib        = (const float*)d_in[6];
    const float* cw        = (const float*)d_in[7];
    const float* cb        = (const float*)d_in[8];
    const float* al        = (const float*)d_in[9];
    const float* sb        = (const float*)d_in[10];
    const float* sc        = (const float*)d_in[11];
    const float* sd        = (const float*)d_in[12];
    const float* ow        = (const float*)d_in[13];
    const float* ob        = (const float*)d_in[14];
    const float* onw       = (const float*)d_in[15];
    const float* onb       = (const float*)d_in[16];
    float* out = (float*)d_out;

    float *px, *ph, *pxin, *pgate, *pu, *pyg, *ps0, *ps1, *ps2, *ps3;
    cudaGetSymbolAddress((void**)&px, g_x);
    cudaGetSymbolAddress((void**)&ph, g_h);
    cudaGetSymbolAddress((void**)&pxin, g_xin);
    cudaGetSymbolAddress((void**)&pgate, g_gate);
    cudaGetSymbolAddress((void**)&pu, g_u);
    cudaGetSymbolAddress((void**)&pyg, g_yg);
    cudaGetSymbolAddress((void**)&ps0, g_s0);
    cudaGetSymbolAddress((void**)&ps1, g_s1);
    cudaGetSymbolAddress((void**)&ps2, g_s2);
    cudaGetSymbolAddress((void**)&ps3, g_s3);

    // in_proj: x = tokens @ in_proj_w + b   (M=16384, N=512, K=768)
    {
        dim3 grid(512 / 128, MTOT / 128);
        gemm_tc_kernel<0><<<grid, 256>>>(tokens, in_proj_w, in_proj_b, px,
                                         nullptr, 512, CC_IN);
    }

    for (int i = 0; i < DEPTH; i++) {
        ln_kernel<<<MTOT / 8, 256>>>(px, nw + i * 512, nb + i * 512, ph);
        {
            dim3 grid(1024 / 128, MTOT / 128);
            gemm_tc_kernel<1><<<grid, 256>>>(ph, iw + (size_t)i * 512 * 1024,
                                             ib + i * 1024, pxin, pgate,
                                             1024, 512);
        }
        conv_kernel<<<XSZ / 256, 256>>>(pxin, cw + i * 9 * 512, cb + i * 512, pu);
        ap_kernel<<<(NN * DD) / 256, 256>>>(al + i * 512);
        scan4_kernel<<<32768 / 128, 128>>>(pu, sb + i * 512, ps0, ps1, ps2, ps3);
        merge_kernel<<<XSZ / 256, 256>>>(ps0, ps1, ps2, ps3, pu, pgate,
                                         sc + i * 512, sd + i * 512, pyg);
        {
            dim3 grid(512 / 128, MTOT / 128);
            gemm_tc_kernel<2><<<grid, 256>>>(pyg, ow + (size_t)i * 512 * 512,
                                             ob + i * 512, px, nullptr,
                                             512, 512);
        }
    }

    ln_kernel<<<MTOT / 8, 256>>>(px, onw, onb, ph);
    pool_kernel<<<16, 512>>>(ph, out);
}